// round 8
// baseline (speedup 1.0000x reference)
#include <cuda_runtime.h>

#define SIZE 256
#define KP 64
#define NB 4
#define NPIX (SIZE * SIZE)
#define NBLK 512          // 4 blocks/SM guaranteed by launch_bounds -> 592 slots >= 512: one wave
#define NTHR 256

typedef unsigned long long u64;

// ---- scratch (device globals; no allocations allowed) ----
__device__ float g_mask[NB * NPIX];
__device__ float g_bmn[NBLK];
__device__ float g_bmx[NBLK];
__device__ unsigned g_cnt = 0;
__device__ volatile unsigned g_gen = 0;

// ---- packed f32x2 helpers (Blackwell sm_100+) ----
__device__ __forceinline__ u64 pk(float lo, float hi) {
    u64 r; asm("mov.b64 %0,{%1,%2};" : "=l"(r) : "f"(lo), "f"(hi)); return r;
}
__device__ __forceinline__ u64 pk2(float s) { return pk(s, s); }
__device__ __forceinline__ void unpk(u64 v, float& lo, float& hi) {
    asm("mov.b64 {%0,%1},%2;" : "=f"(lo), "=f"(hi) : "l"(v));
}
__device__ __forceinline__ u64 pfma(u64 a, u64 b, u64 c) {
    u64 d; asm("fma.rn.f32x2 %0,%1,%2,%3;" : "=l"(d) : "l"(a), "l"(b), "l"(c)); return d;
}
__device__ __forceinline__ u64 pmul(u64 a, u64 b) {
    u64 d; asm("mul.rn.f32x2 %0,%1,%2;" : "=l"(d) : "l"(a), "l"(b)); return d;
}
__device__ __forceinline__ u64 padd(u64 a, u64 b) {
    u64 d; asm("add.rn.f32x2 %0,%1,%2;" : "=l"(d) : "l"(a), "l"(b)); return d;
}
__device__ __forceinline__ float frcp(float x) { float y; asm("rcp.approx.f32 %0,%1;" : "=f"(y) : "f"(x)); return y; }
__device__ __forceinline__ float tha(float x)  { float y; asm("tanh.approx.f32 %0,%1;" : "=f"(y) : "f"(x)); return y; }

// ---- one-wave software grid barrier (all NBLK blocks co-resident) ----
__device__ __forceinline__ void grid_sync(unsigned& gen) {
    __syncthreads();
    if (threadIdx.x == 0) {
        gen++;
        __threadfence();
        unsigned a = atomicAdd(&g_cnt, 1);
        if (a == NBLK - 1) {
            g_cnt = 0;
            __threadfence();
            g_gen = gen;
        } else {
            while (g_gen != gen) { }
            __threadfence();
        }
    }
    __syncthreads();
}

// ---- per-2-px summand: tanh(1e5*cross) * clip(atan2(|cross|,dot)) ----------
// Lagrange identity: |d||n| = sqrt(cross^2 + dot^2) -> no norms needed.
// abs/min/max written so ptxas folds |.| into FMNMX/FSETP source modifiers.
__device__ __forceinline__ u64 angle_acc(u64 CR, u64 DT, u64 ACC,
                                         u64 C0, u64 C1, u64 C2, u64 C3, u64 C4, u64 C5,
                                         u64 KB) {
    float c0, c1, d0, d1;
    unpk(CR, c0, c1); unpk(DT, d0, d1);
    float mx0 = fmaxf(fabsf(c0), fabsf(d0));
    float mx1 = fmaxf(fabsf(c1), fabsf(d1));
    float mn0 = fminf(fabsf(c0), fabsf(d0));
    float mn1 = fminf(fabsf(c1), fabsf(d1));
    float q0 = mn0 * frcp(mx0);
    float q1 = mn1 * frcp(mx1);

    u64 Q = pk(q0, q1);
    u64 Z = pmul(Q, Q);
    u64 T = C5;
    T = pfma(Z, T, C4);
    T = pfma(Z, T, C3);
    T = pfma(Z, T, C2);
    T = pfma(Z, T, C1);
    T = pfma(Z, T, C0);
    u64 A = pmul(Q, T);                       // atan(min/max) in [0, pi/4]

    float a0, a1; unpk(A, a0, a1);
    a0 = (fabsf(c0) > fabsf(d0)) ? 1.5707963267948966f - a0 : a0;   // octant fold
    a1 = (fabsf(c1) > fabsf(d1)) ? 1.5707963267948966f - a1 : a1;
    a0 = (d0 < 0.0f) ? 3.1415926535897931f - a0 : a0;   // dot<0 -> obtuse
    a1 = (d1 < 0.0f) ? 3.1415926535897931f - a1 : a1;
    // reproduce reference clip(r, -1+1e-5, 1-1e-5) before acos:
    a0 = fminf(fmaxf(a0, 4.4721584e-3f), 3.1371205f);
    a1 = fminf(fmaxf(a1, 4.4721584e-3f), 3.1371205f);

    u64 CS = pmul(KB, CR);
    float s0, s1; unpk(CS, s0, s1);
    float t0 = tha(s0), t1 = tha(s1);
    return pfma(pk(t0, t1), pk(a0, a1), ACC);
}

// ---------------------------------------------------------------------------
// persistent kernel, 512 blocks: mask (2px/thr, fully-packed inner loop) ->
// sync -> sobel + 3x3 pool + block minmax -> sync -> reduce + normalize
// ---------------------------------------------------------------------------
__global__ void __launch_bounds__(NTHR, 4)
k_all(const float* __restrict__ contour, float* __restrict__ out) {
    __shared__ u64 cx2[KP + 1];      // {cx,cx} duplicated pairs -> LDS.64, no packing movs
    __shared__ u64 cy2[KP + 1];
    __shared__ float sm[20][37];     // mask tile 16x32 + halo 2 (pad col)
    __shared__ float sb[18][35];     // sobel tile + halo 1 (pad col)
    __shared__ float red[16];        // [0..7]=min partials, [8..15]=max partials

    const int blk = blockIdx.x;
    const int t = threadIdx.x;
    const int b = blk >> 7;          // 128 blocks per batch
    const int sub = blk & 127;
    unsigned gen = g_gen;

    // ---------------- phase 1: winding-number soft mask (2 px/thread) -------
    if (t <= KP) {                   // duplicated vertex 0 -> branchless roll
        int k = t & (KP - 1);
        cx2[t] = pk2(contour[b * KP * 2 + k * 2 + 0]);
        cy2[t] = pk2(contour[b * KP * 2 + k * 2 + 1]);
    }
    __syncthreads();

    const int p0 = sub * 512 + t * 2;            // 2 consecutive same-row px
    const float px = (float)(p0 >> 8) * (1.0f / SIZE);
    const float fy = (float)(p0 & 255) * (1.0f / SIZE);

    const u64 NPX = pk2(-px);
    const u64 NPY = pk(-fy, -(fy + 1.0f / SIZE));
    const u64 NEG1 = pk2(-1.0f);
    const u64 KB = pk2(100000.0f);
    const u64 C0 = pk2( 0.99997726f);
    const u64 C1 = pk2(-0.33262347f);
    const u64 C2 = pk2( 0.19354346f);
    const u64 C3 = pk2(-0.11643287f);
    const u64 C4 = pk2( 0.05265332f);
    const u64 C5 = pk2(-0.01172120f);

    u64 DXP = padd(cx2[0], NPX);     // {dx,dx}
    u64 DYP = padd(cy2[0], NPY);
    u64 NDXP = pmul(DXP, NEG1);
    u64 ACC = 0ull;

#pragma unroll 4
    for (int k = 0; k < KP; k++) {
        const u64 DXN = padd(cx2[k + 1], NPX);
        const u64 DYN = padd(cy2[k + 1], NPY);
        u64 CR = pfma(DYP, DXN, pmul(NDXP, DYN));
        u64 DT = pfma(DYP, DYN, pmul(DXP, DXN));
        ACC = angle_acc(CR, DT, ACC, C0, C1, C2, C3, C4, C5, KB);
        DXP = DXN; DYP = DYN; NDXP = pmul(DXN, NEG1);
    }

    {
        float a0, a1; unpk(ACC, a0, a1);
        float2 v;
        v.x = fminf(fabsf(a0) * 0.15915494309189535f, 1.0f);
        v.y = fminf(fabsf(a1) * 0.15915494309189535f, 1.0f);
        *(float2*)&g_mask[b * NPIX + p0] = v;
    }

    grid_sync(gen);   // mask fully written chip-wide

    // ---------------- phase 2: sobel + 3x3 maxpool + block minmax ------------
    // one 16x32 output tile per block; pooled values stay in registers
    const int ti = (sub >> 3) * 16;
    const int tj = (sub & 7) * 32;
    const float* __restrict__ m = g_mask + b * NPIX;

    for (int idx = t; idx < 20 * 36; idx += NTHR) {
        int si = idx / 36, sj = idx - si * 36;
        int gi = min(max(ti - 2 + si, 0), SIZE - 1);
        int gj = min(max(tj - 2 + sj, 0), SIZE - 1);
        sm[si][sj] = m[gi * SIZE + gj];
    }
    __syncthreads();

    for (int idx = t; idx < 18 * 34; idx += NTHR) {
        int si = idx / 34, sj = idx - si * 34;
        int gi = ti - 1 + si, gj = tj - 1 + sj;
        float v = 0.0f;
        if (gi > 0 && gi < SIZE - 1 && gj > 0 && gj < SIZE - 1) {
            float a00 = sm[si][sj],     a01 = sm[si][sj + 1],     a02 = sm[si][sj + 2];
            float a10 = sm[si + 1][sj],                           a12 = sm[si + 1][sj + 2];
            float a20 = sm[si + 2][sj], a21 = sm[si + 2][sj + 1], a22 = sm[si + 2][sj + 2];
            float gx = 2.0f * (a00 - a02) + 4.0f * (a10 - a12) + 2.0f * (a20 - a22);
            float gy = 2.0f * (a00 - a20) + 4.0f * (a01 - a21) + 2.0f * (a02 - a22);
            v = sqrtf(fmaxf(gx * gx + gy * gy, 1e-24f));
        }
        sb[si][sj] = v;
    }
    __syncthreads();

    const int li = t >> 4;            // 0..15 output row within tile
    const int lj = (t & 15) * 2;      // 0,2,...,30 output col base
    float w[4];
#pragma unroll
    for (int c = 0; c < 4; c++)
        w[c] = fmaxf(fmaxf(sb[li][lj + c], sb[li + 1][lj + c]), sb[li + 2][lj + c]);
    const float r0 = fmaxf(fmaxf(w[0], w[1]), w[2]);
    const float r1 = fmaxf(fmaxf(w[1], w[2]), w[3]);

    // block min/max of the 512 pooled values (single shared pass)
    float lmn = fminf(r0, r1);
    float lmx = fmaxf(r0, r1);
#pragma unroll
    for (int off = 16; off > 0; off >>= 1) {
        lmn = fminf(lmn, __shfl_xor_sync(0xffffffffu, lmn, off));
        lmx = fmaxf(lmx, __shfl_xor_sync(0xffffffffu, lmx, off));
    }
    {
        int lane = t & 31, wid = t >> 5;
        __syncthreads();              // red[] reuse safety across phases
        if (lane == 0) { red[wid] = lmn; red[8 + wid] = lmx; }
        __syncthreads();
        if (t == 0) {
            float gmn = red[0], gmx = red[8];
#pragma unroll
            for (int wq = 1; wq < 8; wq++) {
                gmn = fminf(gmn, red[wq]);
                gmx = fmaxf(gmx, red[8 + wq]);
            }
            g_bmn[blk] = gmn;
            g_bmx[blk] = gmx;
        }
    }

    grid_sync(gen);   // all block minmax published

    // ---------------- phase 3: batch minmax reduce + normalize ---------------
    if (t < 128) {
        float x = g_bmn[(b << 7) + t];
        float y = g_bmx[(b << 7) + t];
#pragma unroll
        for (int off = 16; off > 0; off >>= 1) {
            x = fminf(x, __shfl_xor_sync(0xffffffffu, x, off));
            y = fmaxf(y, __shfl_xor_sync(0xffffffffu, y, off));
        }
        if ((t & 31) == 0) { red[t >> 5] = x; red[4 + (t >> 5)] = y; }
    }
    __syncthreads();
    const float mn = fminf(fminf(red[0], red[1]), fminf(red[2], red[3]));
    const float mx = fmaxf(fmaxf(red[4], red[5]), fmaxf(red[6], red[7]));
    const float sc = 1.0f / (mx - mn + 1e-9f);

    float2 o;
    o.x = (r0 - mn) * sc;
    o.y = (r1 - mn) * sc;
    *(float2*)&out[b * NPIX + (ti + li) * SIZE + tj + lj] = o;
}

// ---------------------------------------------------------------------------
extern "C" void kernel_launch(void* const* d_in, const int* in_sizes, int n_in,
                              void* d_out, int out_size) {
    const float* contour = (const float*)d_in[0];
    float* out = (float*)d_out;
    k_all<<<NBLK, NTHR>>>(contour, out);
}

// round 9
// speedup vs baseline: 1.0666x; 1.0666x over previous
#include <cuda_runtime.h>

#define SIZE 256
#define KP 64
#define NB 4
#define NPIX (SIZE * SIZE)
#define NBLK 256          // 2 blocks/SM guaranteed by launch_bounds -> 296 slots >= 256: one wave
#define NTHR 256

typedef unsigned long long u64;

// ---- scratch (device globals; no allocations allowed) ----
__device__ float g_mask[NB * NPIX];
__device__ float g_bmn[NBLK];
__device__ float g_bmx[NBLK];
__device__ unsigned g_cnt = 0;
__device__ volatile unsigned g_gen = 0;

// ---- packed f32x2 helpers (Blackwell sm_100+) ----
__device__ __forceinline__ u64 pk(float lo, float hi) {
    u64 r; asm("mov.b64 %0,{%1,%2};" : "=l"(r) : "f"(lo), "f"(hi)); return r;
}
__device__ __forceinline__ u64 pk2(float s) { return pk(s, s); }
__device__ __forceinline__ void unpk(u64 v, float& lo, float& hi) {
    asm("mov.b64 {%0,%1},%2;" : "=f"(lo), "=f"(hi) : "l"(v));
}
__device__ __forceinline__ u64 pfma(u64 a, u64 b, u64 c) {
    u64 d; asm("fma.rn.f32x2 %0,%1,%2,%3;" : "=l"(d) : "l"(a), "l"(b), "l"(c)); return d;
}
__device__ __forceinline__ u64 pmul(u64 a, u64 b) {
    u64 d; asm("mul.rn.f32x2 %0,%1,%2;" : "=l"(d) : "l"(a), "l"(b)); return d;
}
__device__ __forceinline__ u64 padd(u64 a, u64 b) {
    u64 d; asm("add.rn.f32x2 %0,%1,%2;" : "=l"(d) : "l"(a), "l"(b)); return d;
}
__device__ __forceinline__ float frcp(float x) { float y; asm("rcp.approx.f32 %0,%1;" : "=f"(y) : "f"(x)); return y; }
__device__ __forceinline__ float tha(float x)  { float y; asm("tanh.approx.f32 %0,%1;" : "=f"(y) : "f"(x)); return y; }

// ---- one-wave software grid barrier (all NBLK blocks co-resident) ----
__device__ __forceinline__ void grid_sync(unsigned& gen) {
    __syncthreads();
    if (threadIdx.x == 0) {
        gen++;
        __threadfence();
        unsigned a = atomicAdd(&g_cnt, 1);
        if (a == NBLK - 1) {
            g_cnt = 0;
            __threadfence();
            g_gen = gen;
        } else {
            while (g_gen != gen) { }
            __threadfence();
        }
    }
    __syncthreads();
}

// ---- per-2-px summand: tanh(1e5*cross) * clip(atan2(|cross|,dot)) ----------
// Lagrange identity: |d||n| = sqrt(cross^2 + dot^2) -> no norms needed.
__device__ __forceinline__ u64 angle_acc(u64 CR, u64 DT, u64 ACC,
                                         u64 C0, u64 C1, u64 C2, u64 C3, u64 C4, u64 C5,
                                         u64 KB) {
    float c0, c1, d0, d1;
    unpk(CR, c0, c1); unpk(DT, d0, d1);
    float mx0 = fmaxf(fabsf(c0), fabsf(d0));
    float mx1 = fmaxf(fabsf(c1), fabsf(d1));
    float mn0 = fminf(fabsf(c0), fabsf(d0));
    float mn1 = fminf(fabsf(c1), fabsf(d1));
    float q0 = mn0 * frcp(mx0);
    float q1 = mn1 * frcp(mx1);

    u64 Q = pk(q0, q1);
    u64 Z = pmul(Q, Q);
    u64 T = C5;
    T = pfma(Z, T, C4);
    T = pfma(Z, T, C3);
    T = pfma(Z, T, C2);
    T = pfma(Z, T, C1);
    T = pfma(Z, T, C0);
    u64 A = pmul(Q, T);                       // atan(min/max) in [0, pi/4]

    float a0, a1; unpk(A, a0, a1);
    a0 = (fabsf(c0) > fabsf(d0)) ? 1.5707963267948966f - a0 : a0;   // octant fold
    a1 = (fabsf(c1) > fabsf(d1)) ? 1.5707963267948966f - a1 : a1;
    a0 = (d0 < 0.0f) ? 3.1415926535897931f - a0 : a0;   // dot<0 -> obtuse
    a1 = (d1 < 0.0f) ? 3.1415926535897931f - a1 : a1;
    // reproduce reference clip(r, -1+1e-5, 1-1e-5) before acos:
    a0 = fminf(fmaxf(a0, 4.4721584e-3f), 3.1371205f);
    a1 = fminf(fmaxf(a1, 4.4721584e-3f), 3.1371205f);

    u64 CS = pmul(KB, CR);
    float s0, s1; unpk(CS, s0, s1);
    float t0 = tha(s0), t1 = tha(s1);
    return pfma(pk(t0, t1), pk(a0, a1), ACC);
}

// ---------------------------------------------------------------------------
// persistent kernel, 256 blocks, 128-reg budget: mask (4px/thr = 2 independent
// packed chains) -> sync -> sobel + pool + block minmax (32x32 tile/block,
// pooled values in regs) -> sync -> reduce + normalize
// ---------------------------------------------------------------------------
__global__ void __launch_bounds__(NTHR, 2)
k_all(const float* __restrict__ contour, float* __restrict__ out) {
    __shared__ float cx[KP + 1];
    __shared__ float cy[KP + 1];
    __shared__ float sm[36][37];     // mask tile 32x32 + halo 2 (pad col)
    __shared__ float sb[34][35];     // sobel tile + halo 1 (pad col)
    __shared__ float red[16];        // [0..7]=min partials, [8..15]=max partials

    const int blk = blockIdx.x;
    const int t = threadIdx.x;
    const int b = blk >> 6;          // 64 blocks per batch
    const int sub = blk & 63;
    unsigned gen = g_gen;

    // ---------------- phase 1: winding-number soft mask (4 px/thread) -------
    if (t <= KP) {                   // duplicated vertex 0 -> branchless roll
        int k = t & (KP - 1);
        cx[t] = contour[b * KP * 2 + k * 2 + 0];
        cy[t] = contour[b * KP * 2 + k * 2 + 1];
    }
    __syncthreads();

    const int p0 = sub * 1024 + t * 4;           // 4 consecutive same-row px
    const float px = (float)(p0 >> 8) * (1.0f / SIZE);
    const float fy = (float)(p0 & 255) * (1.0f / SIZE);

    const u64 NPYa = pk(-fy,                 -(fy + 1.0f / SIZE));
    const u64 NPYb = pk(-(fy + 2.0f / SIZE), -(fy + 3.0f / SIZE));
    const u64 KB = pk2(100000.0f);
    const u64 C0 = pk2( 0.99997726f);
    const u64 C1 = pk2(-0.33262347f);
    const u64 C2 = pk2( 0.19354346f);
    const u64 C3 = pk2(-0.11643287f);
    const u64 C4 = pk2( 0.05265332f);
    const u64 C5 = pk2(-0.01172120f);

    float dxp = cx[0] - px;
    u64 CY0 = pk2(cy[0]);
    u64 DYPa = padd(CY0, NPYa);
    u64 DYPb = padd(CY0, NPYb);
    u64 ACCa = 0ull, ACCb = 0ull;

#pragma unroll 4
    for (int k = 0; k < KP; k++) {
        const float dxn = cx[k + 1] - px;
        const u64 CY = pk2(cy[k + 1]);
        const u64 DYNa = padd(CY, NPYa);
        const u64 DYNb = padd(CY, NPYb);
        const u64 PDXN = pk2(dxn);
        const u64 NDXP = pk2(-dxp);
        const u64 PDXX = pk2(dxp * dxn);

        // two independent chains -> 2x ILP through the deep summand
        u64 CRa = pfma(DYPa, PDXN, pmul(NDXP, DYNa));
        u64 DTa = pfma(DYPa, DYNa, PDXX);
        u64 CRb = pfma(DYPb, PDXN, pmul(NDXP, DYNb));
        u64 DTb = pfma(DYPb, DYNb, PDXX);
        ACCa = angle_acc(CRa, DTa, ACCa, C0, C1, C2, C3, C4, C5, KB);
        ACCb = angle_acc(CRb, DTb, ACCb, C0, C1, C2, C3, C4, C5, KB);

        dxp = dxn; DYPa = DYNa; DYPb = DYNb;
    }

    {
        const float IPI2 = 0.15915494309189535f;
        float a0, a1, b0, b1;
        unpk(ACCa, a0, a1); unpk(ACCb, b0, b1);
        float4 v;
        v.x = fminf(fabsf(a0) * IPI2, 1.0f);
        v.y = fminf(fabsf(a1) * IPI2, 1.0f);
        v.z = fminf(fabsf(b0) * IPI2, 1.0f);
        v.w = fminf(fabsf(b1) * IPI2, 1.0f);
        *(float4*)&g_mask[b * NPIX + p0] = v;
    }

    grid_sync(gen);   // mask fully written chip-wide

    // ---------------- phase 2: sobel + 3x3 maxpool + block minmax ------------
    // one 32x32 output tile per block; pooled values stay in registers
    const int ti = (sub >> 3) * 32;
    const int tj = (sub & 7) * 32;
    const float* __restrict__ m = g_mask + b * NPIX;

    for (int idx = t; idx < 36 * 36; idx += NTHR) {
        int si = idx / 36, sj = idx - si * 36;
        int gi = min(max(ti - 2 + si, 0), SIZE - 1);
        int gj = min(max(tj - 2 + sj, 0), SIZE - 1);
        sm[si][sj] = m[gi * SIZE + gj];
    }
    __syncthreads();

    for (int idx = t; idx < 34 * 34; idx += NTHR) {
        int si = idx / 34, sj = idx - si * 34;
        int gi = ti - 1 + si, gj = tj - 1 + sj;
        float v = 0.0f;
        if (gi > 0 && gi < SIZE - 1 && gj > 0 && gj < SIZE - 1) {
            float a00 = sm[si][sj],     a01 = sm[si][sj + 1],     a02 = sm[si][sj + 2];
            float a10 = sm[si + 1][sj],                           a12 = sm[si + 1][sj + 2];
            float a20 = sm[si + 2][sj], a21 = sm[si + 2][sj + 1], a22 = sm[si + 2][sj + 2];
            float gx = 2.0f * (a00 - a02) + 4.0f * (a10 - a12) + 2.0f * (a20 - a22);
            float gy = 2.0f * (a00 - a20) + 4.0f * (a01 - a21) + 2.0f * (a02 - a22);
            v = sqrtf(fmaxf(gx * gx + gy * gy, 1e-24f));
        }
        sb[si][sj] = v;
    }
    __syncthreads();

    const int li = t >> 3;            // 0..31 output row within tile
    const int lj = (t & 7) * 4;       // 0,4,...,28 output col base
    float w[6];
#pragma unroll
    for (int c = 0; c < 6; c++)
        w[c] = fmaxf(fmaxf(sb[li][lj + c], sb[li + 1][lj + c]), sb[li + 2][lj + c]);
    const float r0 = fmaxf(fmaxf(w[0], w[1]), w[2]);
    const float r1 = fmaxf(fmaxf(w[1], w[2]), w[3]);
    const float r2 = fmaxf(fmaxf(w[2], w[3]), w[4]);
    const float r3 = fmaxf(fmaxf(w[3], w[4]), w[5]);

    // block min/max of the 1024 pooled values (single shared pass)
    float lmn = fminf(fminf(r0, r1), fminf(r2, r3));
    float lmx = fmaxf(fmaxf(r0, r1), fmaxf(r2, r3));
#pragma unroll
    for (int off = 16; off > 0; off >>= 1) {
        lmn = fminf(lmn, __shfl_xor_sync(0xffffffffu, lmn, off));
        lmx = fmaxf(lmx, __shfl_xor_sync(0xffffffffu, lmx, off));
    }
    {
        int lane = t & 31, wid = t >> 5;
        __syncthreads();              // red[] reuse safety across phases
        if (lane == 0) { red[wid] = lmn; red[8 + wid] = lmx; }
        __syncthreads();
        if (t == 0) {
            float gmn = red[0], gmx = red[8];
#pragma unroll
            for (int wq = 1; wq < 8; wq++) {
                gmn = fminf(gmn, red[wq]);
                gmx = fmaxf(gmx, red[8 + wq]);
            }
            g_bmn[blk] = gmn;
            g_bmx[blk] = gmx;
        }
    }

    grid_sync(gen);   // all block minmax published

    // ---------------- phase 3: batch minmax reduce + normalize ---------------
    if (t < 64) {
        float x = g_bmn[(b << 6) + t];
        float y = g_bmx[(b << 6) + t];
#pragma unroll
        for (int off = 16; off > 0; off >>= 1) {
            x = fminf(x, __shfl_xor_sync(0xffffffffu, x, off));
            y = fmaxf(y, __shfl_xor_sync(0xffffffffu, y, off));
        }
        if ((t & 31) == 0) { red[t >> 5] = x; red[4 + (t >> 5)] = y; }
    }
    __syncthreads();
    const float mn = fminf(red[0], red[1]);
    const float mx = fmaxf(red[4], red[5]);
    const float sc = 1.0f / (mx - mn + 1e-9f);

    float4 o;
    o.x = (r0 - mn) * sc;
    o.y = (r1 - mn) * sc;
    o.z = (r2 - mn) * sc;
    o.w = (r3 - mn) * sc;
    *(float4*)&out[b * NPIX + (ti + li) * SIZE + tj + lj] = o;
}

// ---------------------------------------------------------------------------
extern "C" void kernel_launch(void* const* d_in, const int* in_sizes, int n_in,
                              void* d_out, int out_size) {
    const float* contour = (const float*)d_in[0];
    float* out = (float*)d_out;
    k_all<<<NBLK, NTHR>>>(contour, out);
}